// round 1
// baseline (speedup 1.0000x reference)
#include <cuda_runtime.h>

// Problem constants (fixed by setup_inputs)
#define N_IN   4096            // in_features  (reduction dim)
#define K_OUT  4096            // out_features
#define GROUPQ 64              // quant group size
#define NGRP   (N_IN / GROUPQ) // 64 groups

// 67 MB dequantized-weight scratch (device global: allocation-free rule)
__device__ float g_W[(size_t)K_OUT * N_IN];

// ---------------------------------------------------------------------------
// Pass 1: dequantize W once per launch.
// W[k,n] = (W_q[k,n] - zeros[k,g]) * scales[k,g] * scale2[k] * mask[k,n]
// Vectorized 4-wide; 4 consecutive n always share a group (GROUPQ=64).
// ---------------------------------------------------------------------------
__global__ void dequant_kernel(const int* __restrict__ W_q,
                               const float* __restrict__ scales,
                               const float* __restrict__ zeros,
                               const int* __restrict__ mask,
                               const float* __restrict__ scale2)
{
    int idx = blockIdx.x * blockDim.x + threadIdx.x;
    int base = idx * 4;
    if (base >= K_OUT * N_IN) return;

    int k = base / N_IN;
    int n = base - k * N_IN;
    int g = n / GROUPQ;

    float s = scales[k * NGRP + g] * scale2[k];
    float z = zeros[k * NGRP + g];

    int4 q = *reinterpret_cast<const int4*>(W_q + base);
    int4 m = *reinterpret_cast<const int4*>(mask + base);

    float4 w;
    w.x = m.x ? ((float)q.x - z) * s : 0.0f;
    w.y = m.y ? ((float)q.y - z) * s : 0.0f;
    w.z = m.z ? ((float)q.z - z) * s : 0.0f;
    w.w = m.w ? ((float)q.w - z) * s : 0.0f;

    *reinterpret_cast<float4*>(g_W + base) = w;
}

// ---------------------------------------------------------------------------
// Pass 2: C[m,k] = A[m,:] . W[k,:] + bias[k]
// Both operands row-major with contiguous reduction dim (A @ B^T form).
// BM=BN=128, BK=16, 256 threads, 8x8 register tile per thread,
// register-staged global prefetch to hide load latency.
// ---------------------------------------------------------------------------
#define BM 128
#define BN 128
#define BK 16
#define TM 8
#define TN 8

__global__ __launch_bounds__(256, 2)
void gemm_kernel(const float* __restrict__ A,
                 const float* __restrict__ Bias,
                 float* __restrict__ C,
                 int M)
{
    __shared__ float As[BK][BM];
    __shared__ float Bs[BK][BN];

    const float* B = g_W;

    const int tid = threadIdx.x;
    const int tx  = tid & 15;        // 0..15 -> N direction
    const int ty  = tid >> 4;        // 0..15 -> M direction

    const int rowBase = blockIdx.y * BM;
    const int colBase = blockIdx.x * BN;

    // Global-load mapping: thread loads 2 float4 per operand per tile.
    const int lr = tid >> 2;         // 0..63 : row within tile (two passes of 64)
    const int lc = (tid & 3) * 4;    // 0,4,8,12 : k-offset within BK

    const float* Aptr = A + (size_t)rowBase * N_IN;
    const float* Bptr = B + (size_t)colBase * N_IN;

    float acc[TM][TN];
    #pragma unroll
    for (int i = 0; i < TM; i++)
        #pragma unroll
        for (int j = 0; j < TN; j++)
            acc[i][j] = 0.0f;

    float4 aReg[2], bReg[2];

    // preload tile 0
    #pragma unroll
    for (int i = 0; i < 2; i++) {
        int r = lr + 64 * i;
        aReg[i] = *reinterpret_cast<const float4*>(Aptr + (size_t)r * N_IN + lc);
        bReg[i] = *reinterpret_cast<const float4*>(Bptr + (size_t)r * N_IN + lc);
    }

    for (int k0 = 0; k0 < N_IN; k0 += BK) {
        // stage registers -> smem (transposed: As[kk][m])
        #pragma unroll
        for (int i = 0; i < 2; i++) {
            int r = lr + 64 * i;
            As[lc + 0][r] = aReg[i].x;
            As[lc + 1][r] = aReg[i].y;
            As[lc + 2][r] = aReg[i].z;
            As[lc + 3][r] = aReg[i].w;
            Bs[lc + 0][r] = bReg[i].x;
            Bs[lc + 1][r] = bReg[i].y;
            Bs[lc + 2][r] = bReg[i].z;
            Bs[lc + 3][r] = bReg[i].w;
        }
        __syncthreads();

        // prefetch next tile into registers while computing this one
        if (k0 + BK < N_IN) {
            #pragma unroll
            for (int i = 0; i < 2; i++) {
                int r = lr + 64 * i;
                aReg[i] = *reinterpret_cast<const float4*>(Aptr + (size_t)r * N_IN + k0 + BK + lc);
                bReg[i] = *reinterpret_cast<const float4*>(Bptr + (size_t)r * N_IN + k0 + BK + lc);
            }
        }

        // compute
        #pragma unroll
        for (int kk = 0; kk < BK; kk++) {
            float ra[TM], rb[TN];
            #pragma unroll
            for (int i = 0; i < TM; i++) ra[i] = As[kk][ty * TM + i];
            #pragma unroll
            for (int j = 0; j < TN; j++) rb[j] = Bs[kk][tx * TN + j];
            #pragma unroll
            for (int i = 0; i < TM; i++)
                #pragma unroll
                for (int j = 0; j < TN; j++)
                    acc[i][j] += ra[i] * rb[j];
        }
        __syncthreads();
    }

    // epilogue: add bias, store as float4
    #pragma unroll
    for (int i = 0; i < TM; i++) {
        int m = rowBase + ty * TM + i;
        #pragma unroll
        for (int j = 0; j < TN; j += 4) {
            int n = colBase + tx * TN + j;
            float4 v;
            v.x = acc[i][j + 0] + Bias[n + 0];
            v.y = acc[i][j + 1] + Bias[n + 1];
            v.z = acc[i][j + 2] + Bias[n + 2];
            v.w = acc[i][j + 3] + Bias[n + 3];
            *reinterpret_cast<float4*>(C + (size_t)m * K_OUT + n) = v;
        }
    }
}

// ---------------------------------------------------------------------------
// Launch: inputs in metadata order:
//   0: x (B,S,N) f32   1: W_q (K,N) i32   2: scales (K,G) f32
//   3: zeros (K,G) f32 4: mask (K,N) i32  5: scale2 (K,1) f32  6: bias (K) f32
// ---------------------------------------------------------------------------
extern "C" void kernel_launch(void* const* d_in, const int* in_sizes, int n_in,
                              void* d_out, int out_size)
{
    const float* x      = (const float*)d_in[0];
    const int*   W_q    = (const int*)  d_in[1];
    const float* scales = (const float*)d_in[2];
    const float* zeros  = (const float*)d_in[3];
    const int*   mask   = (const int*)  d_in[4];
    const float* scale2 = (const float*)d_in[5];
    const float* bias   = (const float*)d_in[6];
    float*       out    = (float*)d_out;

    const int M = in_sizes[0] / N_IN;   // 8192 for B=4,S=2048

    // Pass 1: dequant (4-wide)
    {
        int total4 = (K_OUT * N_IN) / 4;
        int threads = 256;
        int blocks = (total4 + threads - 1) / threads;
        dequant_kernel<<<blocks, threads>>>(W_q, scales, zeros, mask, scale2);
    }

    // Pass 2: GEMM
    {
        dim3 grid(K_OUT / BN, M / BM);
        gemm_kernel<<<grid, 256>>>(x, bias, out, M);
    }
}

// round 3
// speedup vs baseline: 2.7392x; 2.7392x over previous
#include <cuda_runtime.h>
#include <cstdint>

// Problem constants (fixed by setup_inputs)
#define N_IN   4096            // in_features  (reduction dim)
#define K_OUT  4096            // out_features
#define GROUPQ 64
#define NGRP   (N_IN / GROUPQ)

// Dequantized + tf32-rounded weight scratch (67 MB device global)
__device__ float g_W[(size_t)K_OUT * N_IN];

__device__ __forceinline__ float tf32_round(float x) {
    uint32_t u;
    asm("cvt.rna.tf32.f32 %0, %1;" : "=r"(u) : "f"(x));
    return __uint_as_float(u);
}

// ---------------------------------------------------------------------------
// Pass 1: dequantize W and round to tf32 once per launch.
// ---------------------------------------------------------------------------
__global__ void dequant_kernel(const int* __restrict__ W_q,
                               const float* __restrict__ scales,
                               const float* __restrict__ zeros,
                               const int* __restrict__ mask,
                               const float* __restrict__ scale2)
{
    int idx = blockIdx.x * blockDim.x + threadIdx.x;
    int base = idx * 4;
    if (base >= K_OUT * N_IN) return;

    int k = base / N_IN;
    int n = base - k * N_IN;
    int g = n / GROUPQ;

    float s = scales[k * NGRP + g] * scale2[k];
    float z = zeros[k * NGRP + g];

    int4 q = *reinterpret_cast<const int4*>(W_q + base);
    int4 m = *reinterpret_cast<const int4*>(mask + base);

    float4 w;
    w.x = m.x ? tf32_round(((float)q.x - z) * s) : 0.0f;
    w.y = m.y ? tf32_round(((float)q.y - z) * s) : 0.0f;
    w.z = m.z ? tf32_round(((float)q.z - z) * s) : 0.0f;
    w.w = m.w ? tf32_round(((float)q.w - z) * s) : 0.0f;

    *reinterpret_cast<float4*>(g_W + base) = w;
}

// ---------------------------------------------------------------------------
// Pass 2: tensor-core GEMM, C[m,k] = A[m,:] . W[k,:] + bias[k]
// mma.sync.m16n8k8 tf32. Block 128x128xBK16, 8 warps (2M x 4N),
// warp tile 64x32 (4 m-tiles x 4 n-tiles x 2 k-steps = 32 mma/iter).
// ---------------------------------------------------------------------------
#define BM 128
#define BN 128
#define BK 16
#define SPAD 4   // smem row padding -> stride 20 floats (conflict-free frags)

__device__ __forceinline__ void mma_tf32(float* d, const uint32_t* a, const uint32_t* b) {
    asm volatile(
        "mma.sync.aligned.m16n8k8.row.col.f32.tf32.tf32.f32 "
        "{%0,%1,%2,%3}, {%4,%5,%6,%7}, {%8,%9}, {%0,%1,%2,%3};"
        : "+f"(d[0]), "+f"(d[1]), "+f"(d[2]), "+f"(d[3])
        : "r"(a[0]), "r"(a[1]), "r"(a[2]), "r"(a[3]),
          "r"(b[0]), "r"(b[1]));
}

__global__ __launch_bounds__(256, 2)
void gemm_tc_kernel(const float* __restrict__ A,
                    const float* __restrict__ Bias,
                    float* __restrict__ C,
                    int M)
{
    __shared__ float As[BM][BK + SPAD];
    __shared__ float Bs[BN][BK + SPAD];

    const float* B = g_W;

    const int tid  = threadIdx.x;
    const int wid  = tid >> 5;
    const int lane = tid & 31;
    const int warpM = wid & 1;        // 0..1 -> 64-row slab
    const int warpN = wid >> 1;       // 0..3 -> 32-col slab

    const int rowBase = blockIdx.y * BM;
    const int colBase = blockIdx.x * BN;

    // Global-load mapping: each thread 2 float4 per operand per tile.
    const int lr = tid >> 2;          // 0..63 (rows lr and lr+64)
    const int lc = (tid & 3) * 4;     // 0,4,8,12

    const float* Aptr = A + (size_t)rowBase * N_IN;
    const float* Bptr = B + (size_t)colBase * N_IN;

    float acc[4][4][4];
    #pragma unroll
    for (int i = 0; i < 4; i++)
        #pragma unroll
        for (int j = 0; j < 4; j++)
            #pragma unroll
            for (int r = 0; r < 4; r++)
                acc[i][j][r] = 0.0f;

    float4 aReg[2], bReg[2];

    // preload tile 0
    #pragma unroll
    for (int i = 0; i < 2; i++) {
        int r = lr + 64 * i;
        aReg[i] = *reinterpret_cast<const float4*>(Aptr + (size_t)r * N_IN + lc);
        bReg[i] = *reinterpret_cast<const float4*>(Bptr + (size_t)r * N_IN + lc);
    }

    const int fr = lane >> 2;   // 0..7
    const int fc = lane & 3;    // 0..3

    for (int k0 = 0; k0 < N_IN; k0 += BK) {
        // stage: x gets tf32-rounded here; W already rounded in dequant
        #pragma unroll
        for (int i = 0; i < 2; i++) {
            int r = lr + 64 * i;
            As[r][lc + 0] = tf32_round(aReg[i].x);
            As[r][lc + 1] = tf32_round(aReg[i].y);
            As[r][lc + 2] = tf32_round(aReg[i].z);
            As[r][lc + 3] = tf32_round(aReg[i].w);
            Bs[r][lc + 0] = bReg[i].x;
            Bs[r][lc + 1] = bReg[i].y;
            Bs[r][lc + 2] = bReg[i].z;
            Bs[r][lc + 3] = bReg[i].w;
        }
        __syncthreads();

        // prefetch next tile
        if (k0 + BK < N_IN) {
            #pragma unroll
            for (int i = 0; i < 2; i++) {
                int r = lr + 64 * i;
                aReg[i] = *reinterpret_cast<const float4*>(Aptr + (size_t)r * N_IN + k0 + BK + lc);
                bReg[i] = *reinterpret_cast<const float4*>(Bptr + (size_t)r * N_IN + k0 + BK + lc);
            }
        }

        // compute: 2 k-steps of m16n8k8
        #pragma unroll
        for (int ks = 0; ks < 2; ks++) {
            uint32_t af[4][4], bf[4][2];
            #pragma unroll
            for (int mt = 0; mt < 4; mt++) {
                int row = warpM * 64 + mt * 16;
                int col = ks * 8 + fc;
                af[mt][0] = __float_as_uint(As[row + fr    ][col    ]);
                af[mt][1] = __float_as_uint(As[row + fr + 8][col    ]);
                af[mt][2] = __float_as_uint(As[row + fr    ][col + 4]);
                af[mt][3] = __float_as_uint(As[row + fr + 8][col + 4]);
            }
            #pragma unroll
            for (int nt = 0; nt < 4; nt++) {
                int nrow = warpN * 32 + nt * 8 + fr;
                int col  = ks * 8 + fc;
                bf[nt][0] = __float_as_uint(Bs[nrow][col    ]);
                bf[nt][1] = __float_as_uint(Bs[nrow][col + 4]);
            }
            #pragma unroll
            for (int mt = 0; mt < 4; mt++)
                #pragma unroll
                for (int nt = 0; nt < 4; nt++)
                    mma_tf32(acc[mt][nt], af[mt], bf[nt]);
        }
        __syncthreads();
    }

    // epilogue: bias + store (float2 per fragment row)
    #pragma unroll
    for (int mt = 0; mt < 4; mt++) {
        #pragma unroll
        for (int nt = 0; nt < 4; nt++) {
            int m0 = rowBase + warpM * 64 + mt * 16 + fr;
            int n  = colBase + warpN * 32 + nt * 8 + fc * 2;
            float bx = Bias[n], by = Bias[n + 1];
            float2 v0 = { acc[mt][nt][0] + bx, acc[mt][nt][1] + by };
            float2 v1 = { acc[mt][nt][2] + bx, acc[mt][nt][3] + by };
            *reinterpret_cast<float2*>(C + (size_t)m0 * K_OUT + n)       = v0;
            *reinterpret_cast<float2*>(C + (size_t)(m0 + 8) * K_OUT + n) = v1;
        }
    }
}

// ---------------------------------------------------------------------------
extern "C" void kernel_launch(void* const* d_in, const int* in_sizes, int n_in,
                              void* d_out, int out_size)
{
    const float* x      = (const float*)d_in[0];
    const int*   W_q    = (const int*)  d_in[1];
    const float* scales = (const float*)d_in[2];
    const float* zeros  = (const float*)d_in[3];
    const int*   mask   = (const int*)  d_in[4];
    const float* scale2 = (const float*)d_in[5];
    const float* bias   = (const float*)d_in[6];
    float*       out    = (float*)d_out;

    const int M = in_sizes[0] / N_IN;   // 8192

    {
        int total4 = (K_OUT * N_IN) / 4;
        int threads = 256;
        int blocks = (total4 + threads - 1) / threads;
        dequant_kernel<<<blocks, threads>>>(W_q, scales, zeros, mask, scale2);
    }
    {
        dim3 grid(K_OUT / BN, M / BM);
        gemm_tc_kernel<<<grid, 256>>>(x, bias, out, M);
    }
}